// round 11
// baseline (speedup 1.0000x reference)
#include <cuda_runtime.h>
#include <cuda_fp16.h>
#include <cstdint>
#include <cstddef>

#define DIMC 2048
#define HIDC 2730
#define HP   2816           // HID padded: multiple of 128; N-blocks of 128
#define HP2  (2 * HP)       // interleaved gate|up rows
#define NEXP 8
#define NTOK 8192
#define MAXROWS 17408       // 2*NTOK + NEXP*127, rounded to 128

// ---------------- scratch ----------------
__device__ __half g_xh[(size_t)NTOK * DIMC];
__device__ __half g_w13T[(size_t)HP2 * DIMC];            // interleaved [2HP, DIMC]
__device__ __half g_w2T[(size_t)DIMC * HP];
__device__ __half g_e13T[(size_t)NEXP * HP2 * DIMC];
__device__ __half g_e2T[(size_t)NEXP * DIMC * HP];
__device__ __half g_hS[(size_t)NTOK * HP];               // shared-expert h
__device__ __half g_hR[(size_t)MAXROWS * HP];            // routed h (slot rows)
__device__ int    g_counts[NEXP];
__device__ int    g_off[NEXP + 1];
__device__ int    g_cursor[NEXP];
__device__ int    g_rows[MAXROWS];                       // slot -> token
__device__ float  g_swt[MAXROWS];                        // slot -> combine weight (0 = pad)
__device__ int    g_te[NTOK * 2];
__device__ float  g_wtok[NTOK * 2];                      // token -> top-2 weights

// ---------------- helpers ----------------
__device__ __forceinline__ void cpasync16(uint32_t dst, const void* src) {
    asm volatile("cp.async.cg.shared.global [%0], [%1], 16;\n" :: "r"(dst), "l"(src));
}
__device__ __forceinline__ void ldsm4(uint32_t& r0, uint32_t& r1, uint32_t& r2, uint32_t& r3,
                                      uint32_t addr) {
    asm volatile("ldmatrix.sync.aligned.m8n8.x4.shared.b16 {%0,%1,%2,%3}, [%4];"
        : "=r"(r0), "=r"(r1), "=r"(r2), "=r"(r3) : "r"(addr));
}
__device__ __forceinline__ uint32_t swdst(int row, int c) {
    return (uint32_t)(row * 64 + ((c ^ ((row >> 1) & 3)) << 4));
}
__device__ __forceinline__ void mma_f16(float c[4], const uint32_t a[4], const uint32_t b[2]) {
    asm volatile(
        "mma.sync.aligned.m16n8k16.row.col.f32.f16.f16.f32 "
        "{%0,%1,%2,%3}, {%4,%5,%6,%7}, {%8,%9}, {%0,%1,%2,%3};\n"
        : "+f"(c[0]), "+f"(c[1]), "+f"(c[2]), "+f"(c[3])
        : "r"(a[0]), "r"(a[1]), "r"(a[2]), "r"(a[3]), "r"(b[0]), "r"(b[1]));
}
__device__ __forceinline__ float silu(float v) { return v / (1.f + __expf(-v)); }

// ---------------- small kernels ----------------
__global__ void k_tohalf(const float* __restrict__ in, __half* __restrict__ out, long n4) {
    long i = (long)blockIdx.x * blockDim.x + threadIdx.x;
    if (i >= n4) return;
    float4 v = reinterpret_cast<const float4*>(in)[i];
    __half2 h0 = __floats2half2_rn(v.x, v.y);
    __half2 h1 = __floats2half2_rn(v.z, v.w);
    uint2 u;
    u.x = *reinterpret_cast<uint32_t*>(&h0);
    u.y = *reinterpret_cast<uint32_t*>(&h1);
    reinterpret_cast<uint2*>(out)[i] = u;
}

// transpose + half + pad. mode < 0: out row = oc. mode >= 0 (interleave for w13):
// out row = (oc>>7)*256 + (oc&127) + mode   (mode 0 = gate/w1, 128 = up/w3)
__global__ void k_trans(const float* __restrict__ in, __half* __restrict__ out,
                        int R, int C, int CP, int RP, long inStride, long outStride, int mode) {
    __shared__ float t[32][33];
    const float* ip = in + (size_t)blockIdx.z * inStride;
    __half* op = out + (size_t)blockIdx.z * outStride;
    int c0 = blockIdx.x * 32, r0 = blockIdx.y * 32;
    int tx = threadIdx.x, ty = threadIdx.y;
    #pragma unroll
    for (int i = 0; i < 32; i += 8) {
        int r = r0 + ty + i, c = c0 + tx;
        t[ty + i][tx] = (r < R && c < C) ? ip[(size_t)r * C + c] : 0.f;
    }
    __syncthreads();
    #pragma unroll
    for (int i = 0; i < 32; i += 8) {
        int oc = c0 + ty + i, orr = r0 + tx;
        if (oc < CP && orr < RP) {
            long orow = (mode < 0) ? oc : ((long)(oc >> 7) * 256 + (oc & 127) + mode);
            op[orow * RP + orr] = __float2half_rn(t[tx][ty + i]);
        }
    }
}

__global__ void k_init() {
    int i = blockIdx.x * blockDim.x + threadIdx.x;
    if (i < NEXP) g_counts[i] = 0;
    if (i < MAXROWS) { g_rows[i] = 0; g_swt[i] = 0.f; }
}

__global__ void k_router(const float* __restrict__ x, const float* __restrict__ rw) {
    int gt = blockIdx.x * blockDim.x + threadIdx.x;
    int warp = gt >> 5, lane = gt & 31;
    if (warp >= NTOK) return;
    const float* xr = x + (size_t)warp * DIMC;
    float acc[8] = {0.f,0.f,0.f,0.f,0.f,0.f,0.f,0.f};
    for (int i = 0; i < DIMC / 32; i++) {
        int d = i * 32 + lane;
        float xv = xr[d];
        const float4* p = reinterpret_cast<const float4*>(rw + (size_t)d * NEXP);
        float4 r0 = p[0], r1 = p[1];
        acc[0] += xv * r0.x; acc[1] += xv * r0.y; acc[2] += xv * r0.z; acc[3] += xv * r0.w;
        acc[4] += xv * r1.x; acc[5] += xv * r1.y; acc[6] += xv * r1.z; acc[7] += xv * r1.w;
    }
    #pragma unroll
    for (int e = 0; e < 8; e++) {
        #pragma unroll
        for (int o = 16; o > 0; o >>= 1) acc[e] += __shfl_xor_sync(0xffffffffu, acc[e], o);
    }
    if (lane == 0) {
        int e0 = 0; float l0 = acc[0];
        #pragma unroll
        for (int e = 1; e < 8; e++) if (acc[e] > l0) { l0 = acc[e]; e0 = e; }
        int e1 = 0; float l1 = -3.4e38f;
        #pragma unroll
        for (int e = 0; e < 8; e++) if (e != e0 && acc[e] > l1) { l1 = acc[e]; e1 = e; }
        float w0 = 1.f / (1.f + __expf(l1 - l0));
        g_te[2 * warp] = e0; g_te[2 * warp + 1] = e1;
        g_wtok[2 * warp] = w0; g_wtok[2 * warp + 1] = 1.f - w0;
        atomicAdd(&g_counts[e0], 1);
        atomicAdd(&g_counts[e1], 1);
    }
}

__global__ void k_scan() {
    if (threadIdx.x == 0 && blockIdx.x == 0) {
        int o = 0;
        for (int e = 0; e < NEXP; e++) {
            g_off[e] = o;
            g_cursor[e] = o;
            o += (g_counts[e] + 127) & ~127;
        }
        g_off[NEXP] = o;
    }
}

__global__ void k_assign() {
    int t = blockIdx.x * blockDim.x + threadIdx.x;
    if (t >= NTOK) return;
    #pragma unroll
    for (int k = 0; k < 2; k++) {
        int e = g_te[2 * t + k];
        int p = atomicAdd(&g_cursor[e], 1);
        g_rows[p] = t;
        g_swt[p] = g_wtok[2 * t + k];
    }
}

// ---------- FP16 GEMM 128x256x32, 3-stage, ldmatrix, fused epilogues ----------
// MODE 0: C = fp32 store (C: float*, ldc)
// MODE 1: SwiGLU fuse: tile = [gate(128) | up(128)] for hidden block bn;
//         writes half(silu(g)*u) to H (C: __half*, ldc=HP) at col bn*128
// MODE 2: routed combine: atomicAdd(out[token, col], w_slot * acc)  (C: float*, ldc=DIMC)
#define NSTG 3
#define A_TB 8192
#define B_TB 16384
#define STG_BYTES (A_TB + B_TB)
#define DYN_BYTES (NSTG * STG_BYTES)   // 73728

template <int MODE, bool GATHER, bool EXPERT>
__global__ void __launch_bounds__(256, 1)
k_hgemm(const __half* __restrict__ A, const __half* __restrict__ B,
        void* __restrict__ Cv, int K, int lda, int ldb, int ldc, long bStride) {
    extern __shared__ char smemRaw[];
    __shared__ int rIdx[128];

    int z = blockIdx.z;
    int off = 0;
    if (EXPERT) {
        off = g_off[z];
        int mcount = g_off[z + 1] - off;
        if ((int)blockIdx.y * 128 >= mcount) return;
    }
    int bm = blockIdx.y, bn = blockIdx.x;
    int tid = threadIdx.x;
    int lane = tid & 31, warp = tid >> 5;
    int g = lane >> 2, t4 = lane & 3;
    int wm = warp >> 1, wn = warp & 1;

    uint32_t base = (uint32_t)__cvta_generic_to_shared(smemRaw);

    if (tid < 128) {
        int r = off + bm * 128 + tid;
        rIdx[tid] = GATHER ? g_rows[r] : r;
    }
    __syncthreads();

    // loaders: A = 128 rows x 2 chunks/thread ; B = 256 rows x 4 chunks (row = tid)
    int arl = tid & 127;
    int acp = (tid >> 7) * 2;
    const __half* agp = A + (size_t)rIdx[arl] * lda + acp * 8;
    const __half* Bt = B + (size_t)z * bStride;
    const __half* bgp = Bt + (size_t)(bn * 256 + tid) * ldb;

    auto loadStage = [&](int kt, int s) {
        int k0 = kt * 32;
        uint32_t sa = base + s * STG_BYTES;
        uint32_t sb = sa + A_TB;
        cpasync16(sa + swdst(arl, acp),     agp + k0);
        cpasync16(sa + swdst(arl, acp + 1), agp + k0 + 8);
        #pragma unroll
        for (int c = 0; c < 4; c++)
            cpasync16(sb + swdst(tid, c), bgp + k0 + c * 8);
        asm volatile("cp.async.commit_group;\n");
    };

    int arow[2], achunk0;
    #pragma unroll
    for (int mt = 0; mt < 2; mt++)
        arow[mt] = wm * 32 + mt * 16 + (lane & 7) + (lane & 8);
    achunk0 = lane >> 4;
    int brow[8], bchunk0;
    #pragma unroll
    for (int p = 0; p < 8; p++)
        brow[p] = wn * 128 + p * 16 + (lane & 7) + ((lane >> 1) & 8);
    bchunk0 = (lane >> 3) & 1;

    float c[2][16][4] = {};

    int KT = K >> 5;
    loadStage(0, 0);
    loadStage(1, 1);
    for (int kt = 0; kt < KT; kt++) {
        asm volatile("cp.async.wait_group %0;\n" :: "n"(1));
        __syncthreads();
        if (kt + 2 < KT) loadStage(kt + 2, (kt + 2) % NSTG);
        else asm volatile("cp.async.commit_group;\n");
        int s = kt % NSTG;
        uint32_t sa = base + s * STG_BYTES;
        uint32_t sb = sa + A_TB;
        #pragma unroll
        for (int kk = 0; kk < 2; kk++) {
            uint32_t a[2][4];
            #pragma unroll
            for (int mt = 0; mt < 2; mt++)
                ldsm4(a[mt][0], a[mt][1], a[mt][2], a[mt][3],
                      sa + swdst(arow[mt], kk * 2 + achunk0));
            uint32_t bf[16][2];
            #pragma unroll
            for (int p = 0; p < 8; p++)
                ldsm4(bf[2 * p][0], bf[2 * p][1], bf[2 * p + 1][0], bf[2 * p + 1][1],
                      sb + swdst(brow[p], kk * 2 + bchunk0));
            #pragma unroll
            for (int mt = 0; mt < 2; mt++)
                #pragma unroll
                for (int nt = 0; nt < 16; nt++)
                    mma_f16(c[mt][nt], a[mt], bf[nt]);
        }
        __syncthreads();
    }

    int rowBase = off + bm * 128;

    if (MODE == 0) {
        float* C = (float*)Cv;
        #pragma unroll
        for (int mt = 0; mt < 2; mt++) {
            int rr = rowBase + wm * 32 + mt * 16 + g;
            #pragma unroll
            for (int nt = 0; nt < 16; nt++) {
                int cc = bn * 256 + wn * 128 + nt * 8 + 2 * t4;
                *reinterpret_cast<float2*>(C + (size_t)rr * ldc + cc) =
                    make_float2(c[mt][nt][0], c[mt][nt][1]);
                *reinterpret_cast<float2*>(C + (size_t)(rr + 8) * ldc + cc) =
                    make_float2(c[mt][nt][2], c[mt][nt][3]);
            }
        }
    } else if (MODE == 1) {
        // up warps (wn=1) stage to smem; gate warps (wn=0) fuse silu and store half
        float* su = (float*)smemRaw;   // [128][132] fp32, 67584B < DYN_BYTES
        __syncthreads();
        if (wn == 1) {
            #pragma unroll
            for (int mt = 0; mt < 2; mt++) {
                int r0 = wm * 32 + mt * 16 + g;
                #pragma unroll
                for (int nt = 0; nt < 16; nt++) {
                    int col = nt * 8 + 2 * t4;
                    su[r0 * 132 + col]           = c[mt][nt][0];
                    su[r0 * 132 + col + 1]       = c[mt][nt][1];
                    su[(r0 + 8) * 132 + col]     = c[mt][nt][2];
                    su[(r0 + 8) * 132 + col + 1] = c[mt][nt][3];
                }
            }
        }
        __syncthreads();
        if (wn == 0) {
            __half* H = (__half*)Cv;
            #pragma unroll
            for (int mt = 0; mt < 2; mt++) {
                int r0 = wm * 32 + mt * 16 + g;
                #pragma unroll
                for (int nt = 0; nt < 16; nt++) {
                    int col = nt * 8 + 2 * t4;
                    float u00 = su[r0 * 132 + col],       u01 = su[r0 * 132 + col + 1];
                    float u10 = su[(r0 + 8) * 132 + col], u11 = su[(r0 + 8) * 132 + col + 1];
                    __half2 h0 = __floats2half2_rn(silu(c[mt][nt][0]) * u00,
                                                   silu(c[mt][nt][1]) * u01);
                    __half2 h1 = __floats2half2_rn(silu(c[mt][nt][2]) * u10,
                                                   silu(c[mt][nt][3]) * u11);
                    size_t cbase = (size_t)bn * 128 + col;
                    *reinterpret_cast<__half2*>(H + (size_t)(rowBase + r0) * HP + cbase) = h0;
                    *reinterpret_cast<__half2*>(H + (size_t)(rowBase + r0 + 8) * HP + cbase) = h1;
                }
            }
        }
    } else {
        // MODE 2: weighted atomic combine into out
        float* C = (float*)Cv;
        #pragma unroll
        for (int mt = 0; mt < 2; mt++) {
            int r0 = rowBase + wm * 32 + mt * 16 + g;
            int r1 = r0 + 8;
            float w0 = g_swt[r0], w1 = g_swt[r1];
            int t0 = g_rows[r0], t1 = g_rows[r1];
            float* p0 = C + (size_t)t0 * ldc;
            float* p1 = C + (size_t)t1 * ldc;
            #pragma unroll
            for (int nt = 0; nt < 16; nt++) {
                int cc = bn * 256 + wn * 128 + nt * 8 + 2 * t4;
                if (w0 != 0.f) {
                    atomicAdd(p0 + cc,     w0 * c[mt][nt][0]);
                    atomicAdd(p0 + cc + 1, w0 * c[mt][nt][1]);
                }
                if (w1 != 0.f) {
                    atomicAdd(p1 + cc,     w1 * c[mt][nt][2]);
                    atomicAdd(p1 + cc + 1, w1 * c[mt][nt][3]);
                }
            }
        }
    }
}

// ---------------- host ----------------
extern "C" void kernel_launch(void* const* d_in, const int* in_sizes, int n_in,
                              void* d_out, int out_size) {
    const float* x   = (const float*)d_in[0];
    const float* rw  = (const float*)d_in[1];
    const float* sw1 = (const float*)d_in[2];
    const float* sw2 = (const float*)d_in[3];
    const float* sw3 = (const float*)d_in[4];
    const float* ew1 = (const float*)d_in[5];
    const float* ew2 = (const float*)d_in[6];
    const float* ew3 = (const float*)d_in[7];
    float* out = (float*)d_out;

    __half *xh, *w13, *w2t, *e13, *e2t, *hS, *hR;
    cudaGetSymbolAddress((void**)&xh,  g_xh);
    cudaGetSymbolAddress((void**)&w13, g_w13T);
    cudaGetSymbolAddress((void**)&w2t, g_w2T);
    cudaGetSymbolAddress((void**)&e13, g_e13T);
    cudaGetSymbolAddress((void**)&e2t, g_e2T);
    cudaGetSymbolAddress((void**)&hS,  g_hS);
    cudaGetSymbolAddress((void**)&hR,  g_hR);

    cudaFuncSetAttribute(k_hgemm<1, false, false>, cudaFuncAttributeMaxDynamicSharedMemorySize, DYN_BYTES);
    cudaFuncSetAttribute(k_hgemm<1, true,  true >, cudaFuncAttributeMaxDynamicSharedMemorySize, DYN_BYTES);
    cudaFuncSetAttribute(k_hgemm<0, false, false>, cudaFuncAttributeMaxDynamicSharedMemorySize, DYN_BYTES);
    cudaFuncSetAttribute(k_hgemm<2, false, true >, cudaFuncAttributeMaxDynamicSharedMemorySize, DYN_BYTES);

    k_init<<<(MAXROWS + 255) / 256, 256>>>();
    k_tohalf<<<((NTOK * DIMC / 4) + 255) / 256, 256>>>(x, xh, (long)NTOK * DIMC / 4);

    dim3 tb(32, 8);
    // w1/w3 -> interleaved w13T [HP2, DIMC]
    k_trans<<<dim3(HP / 32, DIMC / 32, 1), tb>>>(sw1, w13, DIMC, HIDC, HP, DIMC, 0, 0, 0);
    k_trans<<<dim3(HP / 32, DIMC / 32, 1), tb>>>(sw3, w13, DIMC, HIDC, HP, DIMC, 0, 0, 128);
    k_trans<<<dim3(HP / 32, DIMC / 32, NEXP), tb>>>(ew1, e13, DIMC, HIDC, HP, DIMC,
                                                    (long)DIMC * HIDC, (long)HP2 * DIMC, 0);
    k_trans<<<dim3(HP / 32, DIMC / 32, NEXP), tb>>>(ew3, e13, DIMC, HIDC, HP, DIMC,
                                                    (long)DIMC * HIDC, (long)HP2 * DIMC, 128);
    // w2 -> [DIMC, HP]
    k_trans<<<dim3(DIMC / 32, HP / 32, 1), tb>>>(sw2, w2t, HIDC, DIMC, DIMC, HP, 0, 0, -1);
    k_trans<<<dim3(DIMC / 32, HP / 32, NEXP), tb>>>(ew2, e2t, HIDC, DIMC, DIMC, HP,
                                                    (long)HIDC * DIMC, (long)DIMC * HP, -1);

    k_router<<<(NTOK * 32 + 255) / 256, 256>>>(x, rw);
    k_scan<<<1, 32>>>();
    k_assign<<<(NTOK + 255) / 256, 256>>>();

    // ---- GEMM1 (fused SwiGLU) ----
    k_hgemm<1, false, false><<<dim3(HP2 / 256, NTOK / 128, 1), 256, DYN_BYTES>>>(
        xh, w13, hS, DIMC, DIMC, DIMC, HP, 0L);
    k_hgemm<1, true, true><<<dim3(HP2 / 256, MAXROWS / 128, NEXP), 256, DYN_BYTES>>>(
        xh, e13, hR, DIMC, DIMC, DIMC, HP, (long)HP2 * DIMC);

    // ---- GEMM2 ----
    k_hgemm<0, false, false><<<dim3(DIMC / 256, NTOK / 128, 1), 256, DYN_BYTES>>>(
        hS, w2t, out, HP, HP, HP, DIMC, 0L);
    k_hgemm<2, false, true><<<dim3(DIMC / 256, MAXROWS / 128, NEXP), 256, DYN_BYTES>>>(
        hR, e2t, out, HP, HP, HP, DIMC, (long)DIMC * HP);
}

// round 13
// speedup vs baseline: 1.0748x; 1.0748x over previous
#include <cuda_runtime.h>
#include <cuda_fp16.h>
#include <cstdint>
#include <cstddef>

#define DIMC 2048
#define HIDC 2730
#define HP   2816           // HID padded: multiple of 64; 64-unit blocks
#define HP2  (2 * HP)       // interleaved gate|up rows (64|64 per 128-block)
#define NEXP 8
#define NTOK 8192
#define MAXROWS 17408       // 2*NTOK + NEXP*127, rounded to 128

// ---------------- scratch ----------------
__device__ __half g_xh[(size_t)NTOK * DIMC];
__device__ __half g_w13T[(size_t)HP2 * DIMC];            // interleaved [2HP, DIMC]
__device__ __half g_w2T[(size_t)DIMC * HP];
__device__ __half g_e13T[(size_t)NEXP * HP2 * DIMC];
__device__ __half g_e2T[(size_t)NEXP * DIMC * HP];
__device__ __half g_hS[(size_t)NTOK * HP];               // shared-expert h
__device__ __half g_hR[(size_t)MAXROWS * HP];            // routed h (slot rows)
__device__ int    g_counts[NEXP];
__device__ int    g_off[NEXP + 1];
__device__ int    g_cursor[NEXP];
__device__ int    g_rows[MAXROWS];                       // slot -> token
__device__ float  g_swt[MAXROWS];                        // slot -> combine weight (0 = pad)
__device__ int    g_te[NTOK * 2];
__device__ float  g_wtok[NTOK * 2];                      // token -> top-2 weights

// ---------------- helpers ----------------
__device__ __forceinline__ void cpasync16(uint32_t dst, const void* src) {
    asm volatile("cp.async.cg.shared.global [%0], [%1], 16;\n" :: "r"(dst), "l"(src));
}
__device__ __forceinline__ void ldsm4(uint32_t& r0, uint32_t& r1, uint32_t& r2, uint32_t& r3,
                                      uint32_t addr) {
    asm volatile("ldmatrix.sync.aligned.m8n8.x4.shared.b16 {%0,%1,%2,%3}, [%4];"
        : "=r"(r0), "=r"(r1), "=r"(r2), "=r"(r3) : "r"(addr));
}
__device__ __forceinline__ uint32_t swdst(int row, int c) {
    return (uint32_t)(row * 64 + ((c ^ ((row >> 1) & 3)) << 4));
}
__device__ __forceinline__ void mma_f16(float c[4], const uint32_t a[4], const uint32_t b[2]) {
    asm volatile(
        "mma.sync.aligned.m16n8k16.row.col.f32.f16.f16.f32 "
        "{%0,%1,%2,%3}, {%4,%5,%6,%7}, {%8,%9}, {%0,%1,%2,%3};\n"
        : "+f"(c[0]), "+f"(c[1]), "+f"(c[2]), "+f"(c[3])
        : "r"(a[0]), "r"(a[1]), "r"(a[2]), "r"(a[3]), "r"(b[0]), "r"(b[1]));
}
__device__ __forceinline__ float silu(float v) { return v / (1.f + __expf(-v)); }

// ---------------- small kernels ----------------
__global__ void k_tohalf(const float* __restrict__ in, __half* __restrict__ out, long n4) {
    long i = (long)blockIdx.x * blockDim.x + threadIdx.x;
    if (i >= n4) return;
    float4 v = reinterpret_cast<const float4*>(in)[i];
    __half2 h0 = __floats2half2_rn(v.x, v.y);
    __half2 h1 = __floats2half2_rn(v.z, v.w);
    uint2 u;
    u.x = *reinterpret_cast<uint32_t*>(&h0);
    u.y = *reinterpret_cast<uint32_t*>(&h1);
    reinterpret_cast<uint2*>(out)[i] = u;
}

// transpose + half + pad. mode < 0: out row = oc.
// mode >= 0 (w13 interleave, 64-unit blocks): out row = (oc>>6)*128 + (oc&63) + mode
//   (mode 0 = gate/w1, 64 = up/w3)
__global__ void k_trans(const float* __restrict__ in, __half* __restrict__ out,
                        int R, int C, int CP, int RP, long inStride, long outStride, int mode) {
    __shared__ float t[32][33];
    const float* ip = in + (size_t)blockIdx.z * inStride;
    __half* op = out + (size_t)blockIdx.z * outStride;
    int c0 = blockIdx.x * 32, r0 = blockIdx.y * 32;
    int tx = threadIdx.x, ty = threadIdx.y;
    #pragma unroll
    for (int i = 0; i < 32; i += 8) {
        int r = r0 + ty + i, c = c0 + tx;
        t[ty + i][tx] = (r < R && c < C) ? ip[(size_t)r * C + c] : 0.f;
    }
    __syncthreads();
    #pragma unroll
    for (int i = 0; i < 32; i += 8) {
        int oc = c0 + ty + i, orr = r0 + tx;
        if (oc < CP && orr < RP) {
            long orow = (mode < 0) ? oc : ((long)(oc >> 6) * 128 + (oc & 63) + mode);
            op[orow * RP + orr] = __float2half_rn(t[tx][ty + i]);
        }
    }
}

__global__ void k_init() {
    int i = blockIdx.x * blockDim.x + threadIdx.x;
    if (i < NEXP) g_counts[i] = 0;
    if (i < MAXROWS) { g_rows[i] = 0; g_swt[i] = 0.f; }
}

__global__ void k_router(const float* __restrict__ x, const float* __restrict__ rw) {
    int gt = blockIdx.x * blockDim.x + threadIdx.x;
    int warp = gt >> 5, lane = gt & 31;
    if (warp >= NTOK) return;
    const float* xr = x + (size_t)warp * DIMC;
    float acc[8] = {0.f,0.f,0.f,0.f,0.f,0.f,0.f,0.f};
    for (int i = 0; i < DIMC / 32; i++) {
        int d = i * 32 + lane;
        float xv = xr[d];
        const float4* p = reinterpret_cast<const float4*>(rw + (size_t)d * NEXP);
        float4 r0 = p[0], r1 = p[1];
        acc[0] += xv * r0.x; acc[1] += xv * r0.y; acc[2] += xv * r0.z; acc[3] += xv * r0.w;
        acc[4] += xv * r1.x; acc[5] += xv * r1.y; acc[6] += xv * r1.z; acc[7] += xv * r1.w;
    }
    #pragma unroll
    for (int e = 0; e < 8; e++) {
        #pragma unroll
        for (int o = 16; o > 0; o >>= 1) acc[e] += __shfl_xor_sync(0xffffffffu, acc[e], o);
    }
    if (lane == 0) {
        int e0 = 0; float l0 = acc[0];
        #pragma unroll
        for (int e = 1; e < 8; e++) if (acc[e] > l0) { l0 = acc[e]; e0 = e; }
        int e1 = 0; float l1 = -3.4e38f;
        #pragma unroll
        for (int e = 0; e < 8; e++) if (e != e0 && acc[e] > l1) { l1 = acc[e]; e1 = e; }
        float w0 = 1.f / (1.f + __expf(l1 - l0));
        g_te[2 * warp] = e0; g_te[2 * warp + 1] = e1;
        g_wtok[2 * warp] = w0; g_wtok[2 * warp + 1] = 1.f - w0;
        atomicAdd(&g_counts[e0], 1);
        atomicAdd(&g_counts[e1], 1);
    }
}

__global__ void k_scan() {
    if (threadIdx.x == 0 && blockIdx.x == 0) {
        int o = 0;
        for (int e = 0; e < NEXP; e++) {
            g_off[e] = o;
            g_cursor[e] = o;
            o += (g_counts[e] + 127) & ~127;
        }
        g_off[NEXP] = o;
    }
}

__global__ void k_assign() {
    int t = blockIdx.x * blockDim.x + threadIdx.x;
    if (t >= NTOK) return;
    #pragma unroll
    for (int k = 0; k < 2; k++) {
        int e = g_te[2 * t + k];
        int p = atomicAdd(&g_cursor[e], 1);
        g_rows[p] = t;
        g_swt[p] = g_wtok[2 * t + k];
    }
}

// ---------- FP16 GEMM 128x128x32, 4-stage, ldmatrix, fused epilogues ----------
// MODE 0: plain fp32 store.
// MODE 1: SwiGLU fuse. Tile n-block bn = [gate(64) | up(64)] for hidden units
//         [bn*64, bn*64+64). wn=1 warps stage 'up' accums to smem; wn=0 warps
//         write half(silu(g)*u) to H at cols bn*64..+63.
// MODE 2: routed combine: atomicAdd(out[token, col], w_slot * acc).
#define NSTG 4
#define TILE_BYTES 8192
#define STG_BYTES 16384
#define DYN_BYTES (NSTG * STG_BYTES)   // 65536

template <int MODE, bool GATHER, bool EXPERT>
__global__ void __launch_bounds__(256, 2)
k_hgemm(const __half* __restrict__ A, const __half* __restrict__ B,
        void* __restrict__ Cv, int K, int lda, int ldb, int ldc, long bStride) {
    extern __shared__ char smemRaw[];
    __shared__ int rIdx[128];

    int z = blockIdx.z;
    int off = 0;
    if (EXPERT) {
        off = g_off[z];
        int mcount = g_off[z + 1] - off;
        if ((int)blockIdx.y * 128 >= mcount) return;
    }
    int bm = blockIdx.y, bn = blockIdx.x;
    int tid = threadIdx.x;
    int lane = tid & 31, warp = tid >> 5;
    int g = lane >> 2, t4 = lane & 3;
    int wm = warp >> 1, wn = warp & 1;

    uint32_t base = (uint32_t)__cvta_generic_to_shared(smemRaw);

    if (tid < 128) {
        int r = off + bm * 128 + tid;
        rIdx[tid] = GATHER ? g_rows[r] : r;
    }
    __syncthreads();

    int lrow = tid & 127;
    int cpair = (tid >> 7) * 2;
    const __half* agp = A + (size_t)rIdx[lrow] * lda + cpair * 8;
    const __half* Bt = B + (size_t)z * bStride;
    const __half* bgp = Bt + (size_t)(bn * 128 + lrow) * ldb + cpair * 8;

    auto loadStage = [&](int kt, int s) {
        int k0 = kt * 32;
        uint32_t sa = base + s * STG_BYTES;
        uint32_t sb = sa + TILE_BYTES;
        cpasync16(sa + swdst(lrow, cpair),     agp + k0);
        cpasync16(sa + swdst(lrow, cpair + 1), agp + k0 + 8);
        cpasync16(sb + swdst(lrow, cpair),     bgp + k0);
        cpasync16(sb + swdst(lrow, cpair + 1), bgp + k0 + 8);
        asm volatile("cp.async.commit_group;\n");
    };

    int arow[2], achunk0;
    #pragma unroll
    for (int mt = 0; mt < 2; mt++)
        arow[mt] = wm * 32 + mt * 16 + (lane & 7) + (lane & 8);
    achunk0 = lane >> 4;
    int brow[4], bchunk0;
    #pragma unroll
    for (int p = 0; p < 4; p++)
        brow[p] = wn * 64 + p * 16 + (lane & 7) + ((lane >> 1) & 8);
    bchunk0 = (lane >> 3) & 1;

    float c[2][8][4] = {};

    int KT = K >> 5;
    loadStage(0, 0);
    loadStage(1, 1);
    loadStage(2, 2);
    for (int kt = 0; kt < KT; kt++) {
        asm volatile("cp.async.wait_group %0;\n" :: "n"(2));
        __syncthreads();
        if (kt + 3 < KT) loadStage(kt + 3, (kt + 3) & 3);
        else asm volatile("cp.async.commit_group;\n");
        int s = kt & 3;
        uint32_t sa = base + s * STG_BYTES;
        uint32_t sb = sa + TILE_BYTES;
        #pragma unroll
        for (int kk = 0; kk < 2; kk++) {
            uint32_t a[2][4];
            #pragma unroll
            for (int mt = 0; mt < 2; mt++)
                ldsm4(a[mt][0], a[mt][1], a[mt][2], a[mt][3],
                      sa + swdst(arow[mt], kk * 2 + achunk0));
            uint32_t bf[8][2];
            #pragma unroll
            for (int p = 0; p < 4; p++)
                ldsm4(bf[2 * p][0], bf[2 * p][1], bf[2 * p + 1][0], bf[2 * p + 1][1],
                      sb + swdst(brow[p], kk * 2 + bchunk0));
            #pragma unroll
            for (int mt = 0; mt < 2; mt++)
                #pragma unroll
                for (int nt = 0; nt < 8; nt++)
                    mma_f16(c[mt][nt], a[mt], bf[nt]);
        }
        __syncthreads();
    }

    int rowBase = off + bm * 128;

    if (MODE == 0) {
        float* C = (float*)Cv;
        #pragma unroll
        for (int mt = 0; mt < 2; mt++) {
            int rr = rowBase + wm * 32 + mt * 16 + g;
            #pragma unroll
            for (int nt = 0; nt < 8; nt++) {
                int cc = bn * 128 + wn * 64 + nt * 8 + 2 * t4;
                *reinterpret_cast<float2*>(C + (size_t)rr * ldc + cc) =
                    make_float2(c[mt][nt][0], c[mt][nt][1]);
                *reinterpret_cast<float2*>(C + (size_t)(rr + 8) * ldc + cc) =
                    make_float2(c[mt][nt][2], c[mt][nt][3]);
            }
        }
    } else if (MODE == 1) {
        // up warps (wn=1, cols 64-127 = up[0..63]) stage; gate warps fuse+store
        float* su = (float*)smemRaw;   // [128][68] fp32 = 34816B <= 65536
        __syncthreads();
        if (wn == 1) {
            #pragma unroll
            for (int mt = 0; mt < 2; mt++) {
                int r0 = wm * 32 + mt * 16 + g;
                #pragma unroll
                for (int nt = 0; nt < 8; nt++) {
                    int col = nt * 8 + 2 * t4;
                    su[r0 * 68 + col]           = c[mt][nt][0];
                    su[r0 * 68 + col + 1]       = c[mt][nt][1];
                    su[(r0 + 8) * 68 + col]     = c[mt][nt][2];
                    su[(r0 + 8) * 68 + col + 1] = c[mt][nt][3];
                }
            }
        }
        __syncthreads();
        if (wn == 0) {
            __half* H = (__half*)Cv;
            #pragma unroll
            for (int mt = 0; mt < 2; mt++) {
                int r0 = wm * 32 + mt * 16 + g;
                #pragma unroll
                for (int nt = 0; nt < 8; nt++) {
                    int col = nt * 8 + 2 * t4;
                    float u00 = su[r0 * 68 + col],       u01 = su[r0 * 68 + col + 1];
                    float u10 = su[(r0 + 8) * 68 + col], u11 = su[(r0 + 8) * 68 + col + 1];
                    __half2 h0 = __floats2half2_rn(silu(c[mt][nt][0]) * u00,
                                                   silu(c[mt][nt][1]) * u01);
                    __half2 h1 = __floats2half2_rn(silu(c[mt][nt][2]) * u10,
                                                   silu(c[mt][nt][3]) * u11);
                    size_t cbase = (size_t)bn * 64 + col;
                    *reinterpret_cast<__half2*>(H + (size_t)(rowBase + r0) * HP + cbase) = h0;
                    *reinterpret_cast<__half2*>(H + (size_t)(rowBase + r0 + 8) * HP + cbase) = h1;
                }
            }
        }
    } else {
        // MODE 2: weighted atomic combine into out
        float* C = (float*)Cv;
        #pragma unroll
        for (int mt = 0; mt < 2; mt++) {
            int r0 = rowBase + wm * 32 + mt * 16 + g;
            int r1 = r0 + 8;
            float w0 = g_swt[r0], w1 = g_swt[r1];
            int t0 = g_rows[r0], t1 = g_rows[r1];
            float* p0 = C + (size_t)t0 * ldc;
            float* p1 = C + (size_t)t1 * ldc;
            #pragma unroll
            for (int nt = 0; nt < 8; nt++) {
                int cc = bn * 128 + wn * 64 + nt * 8 + 2 * t4;
                if (w0 != 0.f) {
                    atomicAdd(p0 + cc,     w0 * c[mt][nt][0]);
                    atomicAdd(p0 + cc + 1, w0 * c[mt][nt][1]);
                }
                if (w1 != 0.f) {
                    atomicAdd(p1 + cc,     w1 * c[mt][nt][2]);
                    atomicAdd(p1 + cc + 1, w1 * c[mt][nt][3]);
                }
            }
        }
    }
}

// ---------------- host ----------------
extern "C" void kernel_launch(void* const* d_in, const int* in_sizes, int n_in,
                              void* d_out, int out_size) {
    const float* x   = (const float*)d_in[0];
    const float* rw  = (const float*)d_in[1];
    const float* sw1 = (const float*)d_in[2];
    const float* sw2 = (const float*)d_in[3];
    const float* sw3 = (const float*)d_in[4];
    const float* ew1 = (const float*)d_in[5];
    const float* ew2 = (const float*)d_in[6];
    const float* ew3 = (const float*)d_in[7];
    float* out = (float*)d_out;

    __half *xh, *w13, *w2t, *e13, *e2t, *hS, *hR;
    cudaGetSymbolAddress((void**)&xh,  g_xh);
    cudaGetSymbolAddress((void**)&w13, g_w13T);
    cudaGetSymbolAddress((void**)&w2t, g_w2T);
    cudaGetSymbolAddress((void**)&e13, g_e13T);
    cudaGetSymbolAddress((void**)&e2t, g_e2T);
    cudaGetSymbolAddress((void**)&hS,  g_hS);
    cudaGetSymbolAddress((void**)&hR,  g_hR);

    cudaFuncSetAttribute(k_hgemm<1, false, false>, cudaFuncAttributeMaxDynamicSharedMemorySize, DYN_BYTES);
    cudaFuncSetAttribute(k_hgemm<1, true,  true >, cudaFuncAttributeMaxDynamicSharedMemorySize, DYN_BYTES);
    cudaFuncSetAttribute(k_hgemm<0, false, false>, cudaFuncAttributeMaxDynamicSharedMemorySize, DYN_BYTES);
    cudaFuncSetAttribute(k_hgemm<2, false, true >, cudaFuncAttributeMaxDynamicSharedMemorySize, DYN_BYTES);

    k_init<<<(MAXROWS + 255) / 256, 256>>>();
    k_tohalf<<<((NTOK * DIMC / 4) + 255) / 256, 256>>>(x, xh, (long)NTOK * DIMC / 4);

    dim3 tb(32, 8);
    // w1/w3 -> interleaved w13T [HP2, DIMC] (64-unit blocks: gate|up)
    k_trans<<<dim3(HP / 32, DIMC / 32, 1), tb>>>(sw1, w13, DIMC, HIDC, HP, DIMC, 0, 0, 0);
    k_trans<<<dim3(HP / 32, DIMC / 32, 1), tb>>>(sw3, w13, DIMC, HIDC, HP, DIMC, 0, 0, 64);
    k_trans<<<dim3(HP / 32, DIMC / 32, NEXP), tb>>>(ew1, e13, DIMC, HIDC, HP, DIMC,
                                                    (long)DIMC * HIDC, (long)HP2 * DIMC, 0);
    k_trans<<<dim3(HP / 32, DIMC / 32, NEXP), tb>>>(ew3, e13, DIMC, HIDC, HP, DIMC,
                                                    (long)DIMC * HIDC, (long)HP2 * DIMC, 64);
    // w2 -> [DIMC, HP]
    k_trans<<<dim3(DIMC / 32, HP / 32, 1), tb>>>(sw2, w2t, HIDC, DIMC, DIMC, HP, 0, 0, -1);
    k_trans<<<dim3(DIMC / 32, HP / 32, NEXP), tb>>>(ew2, e2t, HIDC, DIMC, DIMC, HP,
                                                    (long)HIDC * DIMC, (long)DIMC * HP, -1);

    k_router<<<(NTOK * 32 + 255) / 256, 256>>>(x, rw);
    k_scan<<<1, 32>>>();
    k_assign<<<(NTOK + 255) / 256, 256>>>();

    // ---- GEMM1 (fused SwiGLU) ----
    k_hgemm<1, false, false><<<dim3(HP2 / 128, NTOK / 128, 1), 256, DYN_BYTES>>>(
        xh, w13, hS, DIMC, DIMC, DIMC, HP, 0L);
    k_hgemm<1, true, true><<<dim3(HP2 / 128, MAXROWS / 128, NEXP), 256, DYN_BYTES>>>(
        xh, e13, hR, DIMC, DIMC, DIMC, HP, (long)HP2 * DIMC);

    // ---- GEMM2 ----
    k_hgemm<0, false, false><<<dim3(DIMC / 128, NTOK / 128, 1), 256, DYN_BYTES>>>(
        hS, w2t, out, HP, HP, HP, DIMC, 0L);
    k_hgemm<2, false, true><<<dim3(DIMC / 128, MAXROWS / 128, NEXP), 256, DYN_BYTES>>>(
        hR, e2t, out, HP, HP, HP, DIMC, (long)DIMC * HP);
}

// round 14
// speedup vs baseline: 1.0944x; 1.0183x over previous
#include <cuda_runtime.h>
#include <cuda_fp16.h>
#include <cstdint>
#include <cstddef>

#define DIMC 2048
#define HIDC 2730
#define HP   2816           // HID padded: multiple of 64; 64-unit blocks
#define HP2  (2 * HP)       // interleaved gate|up rows (64|64 per 128-block)
#define NEXP 8
#define NTOK 8192
#define MAXROWS 17408       // 2*NTOK + NEXP*127, rounded to 128

// ---------------- scratch ----------------
__device__ __half g_xh[(size_t)NTOK * DIMC];
__device__ __half g_w13T[(size_t)HP2 * DIMC];            // interleaved [2HP, DIMC]
__device__ __half g_w2T[(size_t)DIMC * HP];
__device__ __half g_e13T[(size_t)NEXP * HP2 * DIMC];
__device__ __half g_e2T[(size_t)NEXP * DIMC * HP];
__device__ __half g_hS[(size_t)NTOK * HP];               // shared-expert h
__device__ __half g_hR[(size_t)MAXROWS * HP];            // routed h (slot rows)
__device__ int    g_counts[NEXP];
__device__ int    g_off[NEXP + 1];
__device__ int    g_cursor[NEXP];
__device__ int    g_rows[MAXROWS];                       // slot -> token
__device__ float  g_swt[MAXROWS];                        // slot -> combine weight (0 = pad)
__device__ int    g_te[NTOK * 2];
__device__ float  g_wtok[NTOK * 2];                      // token -> top-2 weights

// ---------------- helpers ----------------
__device__ __forceinline__ void cpasync16(uint32_t dst, const void* src) {
    asm volatile("cp.async.cg.shared.global [%0], [%1], 16;\n" :: "r"(dst), "l"(src));
}
__device__ __forceinline__ void ldsm4(uint32_t& r0, uint32_t& r1, uint32_t& r2, uint32_t& r3,
                                      uint32_t addr) {
    asm volatile("ldmatrix.sync.aligned.m8n8.x4.shared.b16 {%0,%1,%2,%3}, [%4];"
        : "=r"(r0), "=r"(r1), "=r"(r2), "=r"(r3) : "r"(addr));
}
__device__ __forceinline__ uint32_t swdst(int row, int c) {
    return (uint32_t)(row * 64 + ((c ^ ((row >> 1) & 3)) << 4));
}
__device__ __forceinline__ void mma_f16(float c[4], const uint32_t a[4], const uint32_t b[2]) {
    asm volatile(
        "mma.sync.aligned.m16n8k16.row.col.f32.f16.f16.f32 "
        "{%0,%1,%2,%3}, {%4,%5,%6,%7}, {%8,%9}, {%0,%1,%2,%3};\n"
        : "+f"(c[0]), "+f"(c[1]), "+f"(c[2]), "+f"(c[3])
        : "r"(a[0]), "r"(a[1]), "r"(a[2]), "r"(a[3]), "r"(b[0]), "r"(b[1]));
}
__device__ __forceinline__ float silu(float v) { return v / (1.f + __expf(-v)); }

// ---------------- small kernels ----------------
__global__ void k_tohalf(const float* __restrict__ in, __half* __restrict__ out, long n4) {
    long i = (long)blockIdx.x * blockDim.x + threadIdx.x;
    if (i >= n4) return;
    float4 v = reinterpret_cast<const float4*>(in)[i];
    __half2 h0 = __floats2half2_rn(v.x, v.y);
    __half2 h1 = __floats2half2_rn(v.z, v.w);
    uint2 u;
    u.x = *reinterpret_cast<uint32_t*>(&h0);
    u.y = *reinterpret_cast<uint32_t*>(&h1);
    reinterpret_cast<uint2*>(out)[i] = u;
}

// Vectorized transpose + half + pad. 64x64 tile, float2 loads, half2 stores.
// mode < 0: out row = oc. mode >= 0 (w13 interleave, 64-blocks):
//   out row = (oc>>6)*128 + (oc&63) + mode   (0 = gate/w1, 64 = up/w3)
// Requires: C even, RP even, CP & RP multiples of 64 covered by grid.
__global__ void k_trans(const float* __restrict__ in, __half* __restrict__ out,
                        int R, int C, int CP, int RP, long inStride, long outStride, int mode) {
    __shared__ float s[64][65];
    const float* ip = in + (size_t)blockIdx.z * inStride;
    __half* op = out + (size_t)blockIdx.z * outStride;
    int c0 = blockIdx.x * 64, r0 = blockIdx.y * 64;
    int t = threadIdx.x;                   // 256
    int lr8 = t >> 5;                      // 0..7
    int lc2 = (t & 31) * 2;                // 0..62 (col within tile)
    #pragma unroll
    for (int i = 0; i < 8; i++) {
        int rr = lr8 + i * 8;              // 0..63
        int r = r0 + rr, cc = c0 + lc2;
        float2 v = make_float2(0.f, 0.f);
        if (r < R && cc + 1 < C)
            v = *reinterpret_cast<const float2*>(ip + (size_t)r * C + cc);
        s[rr][lc2] = v.x;
        s[rr][lc2 + 1] = v.y;
    }
    __syncthreads();
    #pragma unroll
    for (int i = 0; i < 8; i++) {
        int ocl = lr8 + i * 8;             // 0..63 (col of tile = out row)
        int oc = c0 + ocl;
        if (oc < CP) {
            long orow = (mode < 0) ? oc : ((long)(oc >> 6) * 128 + (oc & 63) + mode);
            __half2 h = __floats2half2_rn(s[lc2][ocl], s[lc2 + 1][ocl]);
            *reinterpret_cast<__half2*>(op + orow * RP + r0 + lc2) = h;
        }
    }
}

__global__ void k_init() {
    int i = blockIdx.x * blockDim.x + threadIdx.x;
    if (i < NEXP) g_counts[i] = 0;
    if (i < MAXROWS) { g_rows[i] = 0; g_swt[i] = 0.f; }
}

__global__ void k_router(const float* __restrict__ x, const float* __restrict__ rw) {
    int gt = blockIdx.x * blockDim.x + threadIdx.x;
    int warp = gt >> 5, lane = gt & 31;
    if (warp >= NTOK) return;
    const float* xr = x + (size_t)warp * DIMC;
    float acc[8] = {0.f,0.f,0.f,0.f,0.f,0.f,0.f,0.f};
    for (int i = 0; i < DIMC / 32; i++) {
        int d = i * 32 + lane;
        float xv = xr[d];
        const float4* p = reinterpret_cast<const float4*>(rw + (size_t)d * NEXP);
        float4 r0 = p[0], r1 = p[1];
        acc[0] += xv * r0.x; acc[1] += xv * r0.y; acc[2] += xv * r0.z; acc[3] += xv * r0.w;
        acc[4] += xv * r1.x; acc[5] += xv * r1.y; acc[6] += xv * r1.z; acc[7] += xv * r1.w;
    }
    #pragma unroll
    for (int e = 0; e < 8; e++) {
        #pragma unroll
        for (int o = 16; o > 0; o >>= 1) acc[e] += __shfl_xor_sync(0xffffffffu, acc[e], o);
    }
    if (lane == 0) {
        int e0 = 0; float l0 = acc[0];
        #pragma unroll
        for (int e = 1; e < 8; e++) if (acc[e] > l0) { l0 = acc[e]; e0 = e; }
        int e1 = 0; float l1 = -3.4e38f;
        #pragma unroll
        for (int e = 0; e < 8; e++) if (e != e0 && acc[e] > l1) { l1 = acc[e]; e1 = e; }
        float w0 = 1.f / (1.f + __expf(l1 - l0));
        g_te[2 * warp] = e0; g_te[2 * warp + 1] = e1;
        g_wtok[2 * warp] = w0; g_wtok[2 * warp + 1] = 1.f - w0;
        atomicAdd(&g_counts[e0], 1);
        atomicAdd(&g_counts[e1], 1);
    }
}

__global__ void k_scan() {
    if (threadIdx.x == 0 && blockIdx.x == 0) {
        int o = 0;
        for (int e = 0; e < NEXP; e++) {
            g_off[e] = o;
            g_cursor[e] = o;
            o += (g_counts[e] + 127) & ~127;
        }
        g_off[NEXP] = o;
    }
}

__global__ void k_assign() {
    int t = blockIdx.x * blockDim.x + threadIdx.x;
    if (t >= NTOK) return;
    #pragma unroll
    for (int k = 0; k < 2; k++) {
        int e = g_te[2 * t + k];
        int p = atomicAdd(&g_cursor[e], 1);
        g_rows[p] = t;
        g_swt[p] = g_wtok[2 * t + k];
    }
}

// ---------- FP16 GEMM 128x128x32, 4-stage, ldmatrix, fused epilogues ----------
// MODE 0: plain fp32 store.
// MODE 1: SwiGLU fuse. Tile n-block bn = [gate(64) | up(64)] for hidden units
//         [bn*64, bn*64+64). wn=1 warps stage 'up' accums to smem; wn=0 warps
//         write half(silu(g)*u) to H at cols bn*64..+63.
// MODE 2: routed combine: atomicAdd(out[token, col], w_slot * acc).
#define NSTG 4
#define TILE_BYTES 8192
#define STG_BYTES 16384
#define DYN_BYTES (NSTG * STG_BYTES)   // 65536

template <int MODE, bool GATHER, bool EXPERT>
__global__ void __launch_bounds__(256, 2)
k_hgemm(const __half* __restrict__ A, const __half* __restrict__ B,
        void* __restrict__ Cv, int K, int lda, int ldb, int ldc, long bStride) {
    extern __shared__ char smemRaw[];
    __shared__ int rIdx[128];

    int z = blockIdx.z;
    int off = 0;
    if (EXPERT) {
        off = g_off[z];
        int mcount = g_off[z + 1] - off;
        if ((int)blockIdx.y * 128 >= mcount) return;
    }
    int bm = blockIdx.y, bn = blockIdx.x;
    int tid = threadIdx.x;
    int lane = tid & 31, warp = tid >> 5;
    int g = lane >> 2, t4 = lane & 3;
    int wm = warp >> 1, wn = warp & 1;

    uint32_t base = (uint32_t)__cvta_generic_to_shared(smemRaw);

    if (tid < 128) {
        int r = off + bm * 128 + tid;
        rIdx[tid] = GATHER ? g_rows[r] : r;
    }
    __syncthreads();

    int lrow = tid & 127;
    int cpair = (tid >> 7) * 2;
    const __half* agp = A + (size_t)rIdx[lrow] * lda + cpair * 8;
    const __half* Bt = B + (size_t)z * bStride;
    const __half* bgp = Bt + (size_t)(bn * 128 + lrow) * ldb + cpair * 8;

    auto loadStage = [&](int kt, int s) {
        int k0 = kt * 32;
        uint32_t sa = base + s * STG_BYTES;
        uint32_t sb = sa + TILE_BYTES;
        cpasync16(sa + swdst(lrow, cpair),     agp + k0);
        cpasync16(sa + swdst(lrow, cpair + 1), agp + k0 + 8);
        cpasync16(sb + swdst(lrow, cpair),     bgp + k0);
        cpasync16(sb + swdst(lrow, cpair + 1), bgp + k0 + 8);
        asm volatile("cp.async.commit_group;\n");
    };

    int arow[2], achunk0;
    #pragma unroll
    for (int mt = 0; mt < 2; mt++)
        arow[mt] = wm * 32 + mt * 16 + (lane & 7) + (lane & 8);
    achunk0 = lane >> 4;
    int brow[4], bchunk0;
    #pragma unroll
    for (int p = 0; p < 4; p++)
        brow[p] = wn * 64 + p * 16 + (lane & 7) + ((lane >> 1) & 8);
    bchunk0 = (lane >> 3) & 1;

    float c[2][8][4] = {};

    int KT = K >> 5;
    loadStage(0, 0);
    loadStage(1, 1);
    loadStage(2, 2);
    for (int kt = 0; kt < KT; kt++) {
        asm volatile("cp.async.wait_group %0;\n" :: "n"(2));
        __syncthreads();
        if (kt + 3 < KT) loadStage(kt + 3, (kt + 3) & 3);
        else asm volatile("cp.async.commit_group;\n");
        int s = kt & 3;
        uint32_t sa = base + s * STG_BYTES;
        uint32_t sb = sa + TILE_BYTES;
        #pragma unroll
        for (int kk = 0; kk < 2; kk++) {
            uint32_t a[2][4];
            #pragma unroll
            for (int mt = 0; mt < 2; mt++)
                ldsm4(a[mt][0], a[mt][1], a[mt][2], a[mt][3],
                      sa + swdst(arow[mt], kk * 2 + achunk0));
            uint32_t bf[8][2];
            #pragma unroll
            for (int p = 0; p < 4; p++)
                ldsm4(bf[2 * p][0], bf[2 * p][1], bf[2 * p + 1][0], bf[2 * p + 1][1],
                      sb + swdst(brow[p], kk * 2 + bchunk0));
            #pragma unroll
            for (int mt = 0; mt < 2; mt++)
                #pragma unroll
                for (int nt = 0; nt < 8; nt++)
                    mma_f16(c[mt][nt], a[mt], bf[nt]);
        }
        __syncthreads();
    }

    int rowBase = off + bm * 128;

    if (MODE == 0) {
        float* C = (float*)Cv;
        #pragma unroll
        for (int mt = 0; mt < 2; mt++) {
            int rr = rowBase + wm * 32 + mt * 16 + g;
            #pragma unroll
            for (int nt = 0; nt < 8; nt++) {
                int cc = bn * 128 + wn * 64 + nt * 8 + 2 * t4;
                *reinterpret_cast<float2*>(C + (size_t)rr * ldc + cc) =
                    make_float2(c[mt][nt][0], c[mt][nt][1]);
                *reinterpret_cast<float2*>(C + (size_t)(rr + 8) * ldc + cc) =
                    make_float2(c[mt][nt][2], c[mt][nt][3]);
            }
        }
    } else if (MODE == 1) {
        // up warps (wn=1, cols 64-127 = up[0..63]) stage; gate warps fuse+store
        float* su = (float*)smemRaw;   // [128][68] fp32 = 34816B <= 65536
        __syncthreads();
        if (wn == 1) {
            #pragma unroll
            for (int mt = 0; mt < 2; mt++) {
                int r0 = wm * 32 + mt * 16 + g;
                #pragma unroll
                for (int nt = 0; nt < 8; nt++) {
                    int col = nt * 8 + 2 * t4;
                    su[r0 * 68 + col]           = c[mt][nt][0];
                    su[r0 * 68 + col + 1]       = c[mt][nt][1];
                    su[(r0 + 8) * 68 + col]     = c[mt][nt][2];
                    su[(r0 + 8) * 68 + col + 1] = c[mt][nt][3];
                }
            }
        }
        __syncthreads();
        if (wn == 0) {
            __half* H = (__half*)Cv;
            #pragma unroll
            for (int mt = 0; mt < 2; mt++) {
                int r0 = wm * 32 + mt * 16 + g;
                #pragma unroll
                for (int nt = 0; nt < 8; nt++) {
                    int col = nt * 8 + 2 * t4;
                    float u00 = su[r0 * 68 + col],       u01 = su[r0 * 68 + col + 1];
                    float u10 = su[(r0 + 8) * 68 + col], u11 = su[(r0 + 8) * 68 + col + 1];
                    __half2 h0 = __floats2half2_rn(silu(c[mt][nt][0]) * u00,
                                                   silu(c[mt][nt][1]) * u01);
                    __half2 h1 = __floats2half2_rn(silu(c[mt][nt][2]) * u10,
                                                   silu(c[mt][nt][3]) * u11);
                    size_t cbase = (size_t)bn * 64 + col;
                    *reinterpret_cast<__half2*>(H + (size_t)(rowBase + r0) * HP + cbase) = h0;
                    *reinterpret_cast<__half2*>(H + (size_t)(rowBase + r0 + 8) * HP + cbase) = h1;
                }
            }
        }
    } else {
        // MODE 2: weighted atomic combine into out
        float* C = (float*)Cv;
        #pragma unroll
        for (int mt = 0; mt < 2; mt++) {
            int r0 = rowBase + wm * 32 + mt * 16 + g;
            int r1 = r0 + 8;
            float w0 = g_swt[r0], w1 = g_swt[r1];
            int t0 = g_rows[r0], t1 = g_rows[r1];
            float* p0 = C + (size_t)t0 * ldc;
            float* p1 = C + (size_t)t1 * ldc;
            #pragma unroll
            for (int nt = 0; nt < 8; nt++) {
                int cc = bn * 128 + wn * 64 + nt * 8 + 2 * t4;
                if (w0 != 0.f) {
                    atomicAdd(p0 + cc,     w0 * c[mt][nt][0]);
                    atomicAdd(p0 + cc + 1, w0 * c[mt][nt][1]);
                }
                if (w1 != 0.f) {
                    atomicAdd(p1 + cc,     w1 * c[mt][nt][2]);
                    atomicAdd(p1 + cc + 1, w1 * c[mt][nt][3]);
                }
            }
        }
    }
}

// ---------------- host ----------------
extern "C" void kernel_launch(void* const* d_in, const int* in_sizes, int n_in,
                              void* d_out, int out_size) {
    const float* x   = (const float*)d_in[0];
    const float* rw  = (const float*)d_in[1];
    const float* sw1 = (const float*)d_in[2];
    const float* sw2 = (const float*)d_in[3];
    const float* sw3 = (const float*)d_in[4];
    const float* ew1 = (const float*)d_in[5];
    const float* ew2 = (const float*)d_in[6];
    const float* ew3 = (const float*)d_in[7];
    float* out = (float*)d_out;

    __half *xh, *w13, *w2t, *e13, *e2t, *hS, *hR;
    cudaGetSymbolAddress((void**)&xh,  g_xh);
    cudaGetSymbolAddress((void**)&w13, g_w13T);
    cudaGetSymbolAddress((void**)&w2t, g_w2T);
    cudaGetSymbolAddress((void**)&e13, g_e13T);
    cudaGetSymbolAddress((void**)&e2t, g_e2T);
    cudaGetSymbolAddress((void**)&hS,  g_hS);
    cudaGetSymbolAddress((void**)&hR,  g_hR);

    cudaFuncSetAttribute(k_hgemm<1, false, false>, cudaFuncAttributeMaxDynamicSharedMemorySize, DYN_BYTES);
    cudaFuncSetAttribute(k_hgemm<1, true,  true >, cudaFuncAttributeMaxDynamicSharedMemorySize, DYN_BYTES);
    cudaFuncSetAttribute(k_hgemm<0, false, false>, cudaFuncAttributeMaxDynamicSharedMemorySize, DYN_BYTES);
    cudaFuncSetAttribute(k_hgemm<2, false, true >, cudaFuncAttributeMaxDynamicSharedMemorySize, DYN_BYTES);

    dim3 tb(256);
    // Launches 1-5 (so the 6th = shared GEMM1 lands under ncu's -s 5 -c 1):
    k_trans<<<dim3(HP / 64, DIMC / 64, 1), tb>>>(sw1, w13, DIMC, HIDC, HP, DIMC, 0, 0, 0);
    k_trans<<<dim3(HP / 64, DIMC / 64, 1), tb>>>(sw3, w13, DIMC, HIDC, HP, DIMC, 0, 0, 64);
    k_tohalf<<<((NTOK * DIMC / 4) + 255) / 256, 256>>>(x, xh, (long)NTOK * DIMC / 4);
    k_init<<<(MAXROWS + 255) / 256, 256>>>();
    k_router<<<(NTOK * 32 + 255) / 256, 256>>>(x, rw);

    // ---- launch 6: shared GEMM1 (fused SwiGLU) — ncu capture target ----
    k_hgemm<1, false, false><<<dim3(HP2 / 128, NTOK / 128, 1), 256, DYN_BYTES>>>(
        xh, w13, hS, DIMC, DIMC, DIMC, HP, 0L);

    // remaining prepass
    k_trans<<<dim3(DIMC / 64, HP / 64, 1), tb>>>(sw2, w2t, HIDC, DIMC, DIMC, HP, 0, 0, -1);
    k_trans<<<dim3(HP / 64, DIMC / 64, NEXP), tb>>>(ew1, e13, DIMC, HIDC, HP, DIMC,
                                                    (long)DIMC * HIDC, (long)HP2 * DIMC, 0);
    k_trans<<<dim3(HP / 64, DIMC / 64, NEXP), tb>>>(ew3, e13, DIMC, HIDC, HP, DIMC,
                                                    (long)DIMC * HIDC, (long)HP2 * DIMC, 64);
    k_trans<<<dim3(DIMC / 64, HP / 64, NEXP), tb>>>(ew2, e2t, HIDC, DIMC, DIMC, HP,
                                                    (long)HIDC * DIMC, (long)DIMC * HP, -1);
    k_scan<<<1, 32>>>();
    k_assign<<<(NTOK + 255) / 256, 256>>>();

    // ---- shared GEMM2 ----
    k_hgemm<0, false, false><<<dim3(DIMC / 128, NTOK / 128, 1), 256, DYN_BYTES>>>(
        hS, w2t, out, HP, HP, HP, DIMC, 0L);

    // ---- routed GEMM1 + GEMM2 ----
    k_hgemm<1, true, true><<<dim3(HP2 / 128, MAXROWS / 128, NEXP), 256, DYN_BYTES>>>(
        xh, e13, hR, DIMC, DIMC, DIMC, HP, (long)HP2 * DIMC);
    k_hgemm<2, false, true><<<dim3(DIMC / 128, MAXROWS / 128, NEXP), 256, DYN_BYTES>>>(
        hR, e2t, out, HP, HP, HP, DIMC, (long)DIMC * HP);
}

// round 16
// speedup vs baseline: 1.0995x; 1.0047x over previous
#include <cuda_runtime.h>
#include <cuda_fp16.h>
#include <cstdint>
#include <cstddef>

#define DIMC 2048
#define HIDC 2730
#define HP   2816           // HID padded: multiple of 64; 64-unit blocks
#define HP2  (2 * HP)       // interleaved gate|up rows (64|64 per 128-block)
#define NEXP 8
#define NTOK 8192
#define MAXROWS 17408       // 2*NTOK + NEXP*127, rounded to 128
#define MAXTILES (MAXROWS / 128)   // 136

// ---------------- scratch ----------------
__device__ __half g_xh[(size_t)NTOK * DIMC];
__device__ __half g_w13T[(size_t)HP2 * DIMC];            // interleaved [2HP, DIMC]
__device__ __half g_w2T[(size_t)DIMC * HP];
__device__ __half g_e13T[(size_t)NEXP * HP2 * DIMC];
__device__ __half g_e2T[(size_t)NEXP * DIMC * HP];
__device__ __half g_hS[(size_t)NTOK * HP];               // shared-expert h
__device__ __half g_hR[(size_t)MAXROWS * HP];            // routed h (slot rows)
__device__ int    g_counts[NEXP];
__device__ int    g_off[NEXP + 1];
__device__ int    g_cursor[NEXP];
__device__ int    g_rows[MAXROWS];                       // slot -> token
__device__ float  g_swt[MAXROWS];                        // slot -> combine weight (0 = pad)
__device__ int    g_te[NTOK * 2];
__device__ float  g_wtok[NTOK * 2];                      // token -> top-2 weights

// ---------------- helpers ----------------
__device__ __forceinline__ void cpasync16(uint32_t dst, const void* src) {
    asm volatile("cp.async.cg.shared.global [%0], [%1], 16;\n" :: "r"(dst), "l"(src));
}
__device__ __forceinline__ void ldsm4(uint32_t& r0, uint32_t& r1, uint32_t& r2, uint32_t& r3,
                                      uint32_t addr) {
    asm volatile("ldmatrix.sync.aligned.m8n8.x4.shared.b16 {%0,%1,%2,%3}, [%4];"
        : "=r"(r0), "=r"(r1), "=r"(r2), "=r"(r3) : "r"(addr));
}
__device__ __forceinline__ uint32_t swdst(int row, int c) {
    return (uint32_t)(row * 64 + ((c ^ ((row >> 1) & 3)) << 4));
}
__device__ __forceinline__ void mma_f16(float c[4], const uint32_t a[4], const uint32_t b[2]) {
    asm volatile(
        "mma.sync.aligned.m16n8k16.row.col.f32.f16.f16.f32 "
        "{%0,%1,%2,%3}, {%4,%5,%6,%7}, {%8,%9}, {%0,%1,%2,%3};\n"
        : "+f"(c[0]), "+f"(c[1]), "+f"(c[2]), "+f"(c[3])
        : "r"(a[0]), "r"(a[1]), "r"(a[2]), "r"(a[3]), "r"(b[0]), "r"(b[1]));
}
__device__ __forceinline__ float silu(float v) { return v / (1.f + __expf(-v)); }

// ---------------- small kernels ----------------
__global__ void k_tohalf(const float* __restrict__ in, __half* __restrict__ out, long n4) {
    long i = (long)blockIdx.x * blockDim.x + threadIdx.x;
    if (i >= n4) return;
    float4 v = reinterpret_cast<const float4*>(in)[i];
    __half2 h0 = __floats2half2_rn(v.x, v.y);
    __half2 h1 = __floats2half2_rn(v.z, v.w);
    uint2 u;
    u.x = *reinterpret_cast<uint32_t*>(&h0);
    u.y = *reinterpret_cast<uint32_t*>(&h1);
    reinterpret_cast<uint2*>(out)[i] = u;
}

// Vectorized transpose + half + pad. 64x64 tile, float2 loads, half2 stores.
// mode < 0: out row = oc. mode >= 0 (w13 interleave, 64-blocks):
//   out row = (oc>>6)*128 + (oc&63) + mode   (0 = gate/w1, 64 = up/w3)
__global__ void k_trans(const float* __restrict__ in, __half* __restrict__ out,
                        int R, int C, int CP, int RP, long inStride, long outStride, int mode) {
    __shared__ float s[64][65];
    const float* ip = in + (size_t)blockIdx.z * inStride;
    __half* op = out + (size_t)blockIdx.z * outStride;
    int c0 = blockIdx.x * 64, r0 = blockIdx.y * 64;
    int t = threadIdx.x;                   // 256
    int lr8 = t >> 5;                      // 0..7
    int lc2 = (t & 31) * 2;                // 0..62
    #pragma unroll
    for (int i = 0; i < 8; i++) {
        int rr = lr8 + i * 8;
        int r = r0 + rr, cc = c0 + lc2;
        float2 v = make_float2(0.f, 0.f);
        if (r < R && cc + 1 < C)
            v = *reinterpret_cast<const float2*>(ip + (size_t)r * C + cc);
        s[rr][lc2] = v.x;
        s[rr][lc2 + 1] = v.y;
    }
    __syncthreads();
    #pragma unroll
    for (int i = 0; i < 8; i++) {
        int ocl = lr8 + i * 8;
        int oc = c0 + ocl;
        if (oc < CP) {
            long orow = (mode < 0) ? oc : ((long)(oc >> 6) * 128 + (oc & 63) + mode);
            __half2 h = __floats2half2_rn(s[lc2][ocl], s[lc2 + 1][ocl]);
            *reinterpret_cast<__half2*>(op + orow * RP + r0 + lc2) = h;
        }
    }
}

__global__ void k_init() {
    int i = blockIdx.x * blockDim.x + threadIdx.x;
    if (i < NEXP) g_counts[i] = 0;
    if (i < MAXROWS) { g_rows[i] = 0; g_swt[i] = 0.f; }
}

__global__ void k_router(const float* __restrict__ x, const float* __restrict__ rw) {
    int gt = blockIdx.x * blockDim.x + threadIdx.x;
    int warp = gt >> 5, lane = gt & 31;
    if (warp >= NTOK) return;
    const float* xr = x + (size_t)warp * DIMC;
    float acc[8] = {0.f,0.f,0.f,0.f,0.f,0.f,0.f,0.f};
    for (int i = 0; i < DIMC / 32; i++) {
        int d = i * 32 + lane;
        float xv = xr[d];
        const float4* p = reinterpret_cast<const float4*>(rw + (size_t)d * NEXP);
        float4 r0 = p[0], r1 = p[1];
        acc[0] += xv * r0.x; acc[1] += xv * r0.y; acc[2] += xv * r0.z; acc[3] += xv * r0.w;
        acc[4] += xv * r1.x; acc[5] += xv * r1.y; acc[6] += xv * r1.z; acc[7] += xv * r1.w;
    }
    #pragma unroll
    for (int e = 0; e < 8; e++) {
        #pragma unroll
        for (int o = 16; o > 0; o >>= 1) acc[e] += __shfl_xor_sync(0xffffffffu, acc[e], o);
    }
    if (lane == 0) {
        int e0 = 0; float l0 = acc[0];
        #pragma unroll
        for (int e = 1; e < 8; e++) if (acc[e] > l0) { l0 = acc[e]; e0 = e; }
        int e1 = 0; float l1 = -3.4e38f;
        #pragma unroll
        for (int e = 0; e < 8; e++) if (e != e0 && acc[e] > l1) { l1 = acc[e]; e1 = e; }
        float w0 = 1.f / (1.f + __expf(l1 - l0));
        g_te[2 * warp] = e0; g_te[2 * warp + 1] = e1;
        g_wtok[2 * warp] = w0; g_wtok[2 * warp + 1] = 1.f - w0;
        atomicAdd(&g_counts[e0], 1);
        atomicAdd(&g_counts[e1], 1);
    }
}

__global__ void k_scan() {
    if (threadIdx.x == 0 && blockIdx.x == 0) {
        int o = 0;
        for (int e = 0; e < NEXP; e++) {
            g_off[e] = o;
            g_cursor[e] = o;
            o += (g_counts[e] + 127) & ~127;
        }
        g_off[NEXP] = o;
    }
}

__global__ void k_assign() {
    int t = blockIdx.x * blockDim.x + threadIdx.x;
    if (t >= NTOK) return;
    #pragma unroll
    for (int k = 0; k < 2; k++) {
        int e = g_te[2 * t + k];
        int p = atomicAdd(&g_cursor[e], 1);
        g_rows[p] = t;
        g_swt[p] = g_wtok[2 * t + k];
    }
}

// ---------- FP16 GEMM 128x128x32, 4-stage, ldmatrix, fused epilogues ----------
// MODE 0: plain fp32 store.
// MODE 1: SwiGLU fuse (gate|up 64|64 n-blocks) -> half h.
// MODE 2: routed combine: atomicAdd(out[token, col], w_slot * acc).
// EXPERT: flat global tile index in blockIdx.y; expert found by scanning g_off
//         (tiles are 128-aligned per expert, so each tile maps to one expert).
#define NSTG 4
#define TILE_BYTES 8192
#define STG_BYTES 16384
#define DYN_BYTES (NSTG * STG_BYTES)   // 65536

template <int MODE, bool GATHER, bool EXPERT>
__global__ void __launch_bounds__(256, 2)
k_hgemm(const __half* __restrict__ A, const __half* __restrict__ B,
        void* __restrict__ Cv, int K, int lda, int ldb, int ldc, long bStride) {
    extern __shared__ char smemRaw[];
    __shared__ int rIdx[128];

    int e = 0;
    int rowBase = blockIdx.y * 128;
    if (EXPERT) {
        if (rowBase >= g_off[NEXP]) return;
        #pragma unroll
        for (int q = 0; q < NEXP - 1; q++)
            if (g_off[q + 1] <= rowBase) e = q + 1;
    }
    int bn = blockIdx.x;
    int tid = threadIdx.x;
    int lane = tid & 31, warp = tid >> 5;
    int g = lane >> 2, t4 = lane & 3;
    int wm = warp >> 1, wn = warp & 1;

    uint32_t base = (uint32_t)__cvta_generic_to_shared(smemRaw);

    if (tid < 128) {
        int r = rowBase + tid;
        rIdx[tid] = GATHER ? g_rows[r] : r;
    }
    __syncthreads();

    int lrow = tid & 127;
    int cpair = (tid >> 7) * 2;
    const __half* agp = A + (size_t)rIdx[lrow] * lda + cpair * 8;
    const __half* Bt = B + (size_t)e * bStride;
    const __half* bgp = Bt + (size_t)(bn * 128 + lrow) * ldb + cpair * 8;

    auto loadStage = [&](int kt, int s) {
        int k0 = kt * 32;
        uint32_t sa = base + s * STG_BYTES;
        uint32_t sb = sa + TILE_BYTES;
        cpasync16(sa + swdst(lrow, cpair),     agp + k0);
        cpasync16(sa + swdst(lrow, cpair + 1), agp + k0 + 8);
        cpasync16(sb + swdst(lrow, cpair),     bgp + k0);
        cpasync16(sb + swdst(lrow, cpair + 1), bgp + k0 + 8);
        asm volatile("cp.async.commit_group;\n");
    };

    int arow[2], achunk0;
    #pragma unroll
    for (int mt = 0; mt < 2; mt++)
        arow[mt] = wm * 32 + mt * 16 + (lane & 7) + (lane & 8);
    achunk0 = lane >> 4;
    int brow[4], bchunk0;
    #pragma unroll
    for (int p = 0; p < 4; p++)
        brow[p] = wn * 64 + p * 16 + (lane & 7) + ((lane >> 1) & 8);
    bchunk0 = (lane >> 3) & 1;

    float c[2][8][4] = {};

    int KT = K >> 5;
    loadStage(0, 0);
    loadStage(1, 1);
    loadStage(2, 2);
    for (int kt = 0; kt < KT; kt++) {
        asm volatile("cp.async.wait_group %0;\n" :: "n"(2));
        __syncthreads();
        if (kt + 3 < KT) loadStage(kt + 3, (kt + 3) & 3);
        else asm volatile("cp.async.commit_group;\n");
        int s = kt & 3;
        uint32_t sa = base + s * STG_BYTES;
        uint32_t sb = sa + TILE_BYTES;
        #pragma unroll
        for (int kk = 0; kk < 2; kk++) {
            uint32_t a[2][4];
            #pragma unroll
            for (int mt = 0; mt < 2; mt++)
                ldsm4(a[mt][0], a[mt][1], a[mt][2], a[mt][3],
                      sa + swdst(arow[mt], kk * 2 + achunk0));
            uint32_t bf[8][2];
            #pragma unroll
            for (int p = 0; p < 4; p++)
                ldsm4(bf[2 * p][0], bf[2 * p][1], bf[2 * p + 1][0], bf[2 * p + 1][1],
                      sb + swdst(brow[p], kk * 2 + bchunk0));
            #pragma unroll
            for (int mt = 0; mt < 2; mt++)
                #pragma unroll
                for (int nt = 0; nt < 8; nt++)
                    mma_f16(c[mt][nt], a[mt], bf[nt]);
        }
        __syncthreads();
    }

    if (MODE == 0) {
        float* C = (float*)Cv;
        #pragma unroll
        for (int mt = 0; mt < 2; mt++) {
            int rr = rowBase + wm * 32 + mt * 16 + g;
            #pragma unroll
            for (int nt = 0; nt < 8; nt++) {
                int cc = bn * 128 + wn * 64 + nt * 8 + 2 * t4;
                *reinterpret_cast<float2*>(C + (size_t)rr * ldc + cc) =
                    make_float2(c[mt][nt][0], c[mt][nt][1]);
                *reinterpret_cast<float2*>(C + (size_t)(rr + 8) * ldc + cc) =
                    make_float2(c[mt][nt][2], c[mt][nt][3]);
            }
        }
    } else if (MODE == 1) {
        float* su = (float*)smemRaw;   // [128][68] fp32 = 34816B <= 65536
        __syncthreads();
        if (wn == 1) {
            #pragma unroll
            for (int mt = 0; mt < 2; mt++) {
                int r0 = wm * 32 + mt * 16 + g;
                #pragma unroll
                for (int nt = 0; nt < 8; nt++) {
                    int col = nt * 8 + 2 * t4;
                    su[r0 * 68 + col]           = c[mt][nt][0];
                    su[r0 * 68 + col + 1]       = c[mt][nt][1];
                    su[(r0 + 8) * 68 + col]     = c[mt][nt][2];
                    su[(r0 + 8) * 68 + col + 1] = c[mt][nt][3];
                }
            }
        }
        __syncthreads();
        if (wn == 0) {
            __half* H = (__half*)Cv;
            #pragma unroll
            for (int mt = 0; mt < 2; mt++) {
                int r0 = wm * 32 + mt * 16 + g;
                #pragma unroll
                for (int nt = 0; nt < 8; nt++) {
                    int col = nt * 8 + 2 * t4;
                    float u00 = su[r0 * 68 + col],       u01 = su[r0 * 68 + col + 1];
                    float u10 = su[(r0 + 8) * 68 + col], u11 = su[(r0 + 8) * 68 + col + 1];
                    __half2 h0 = __floats2half2_rn(silu(c[mt][nt][0]) * u00,
                                                   silu(c[mt][nt][1]) * u01);
                    __half2 h1 = __floats2half2_rn(silu(c[mt][nt][2]) * u10,
                                                   silu(c[mt][nt][3]) * u11);
                    size_t cbase = (size_t)bn * 64 + col;
                    *reinterpret_cast<__half2*>(H + (size_t)(rowBase + r0) * HP + cbase) = h0;
                    *reinterpret_cast<__half2*>(H + (size_t)(rowBase + r0 + 8) * HP + cbase) = h1;
                }
            }
        }
    } else {
        float* C = (float*)Cv;
        #pragma unroll
        for (int mt = 0; mt < 2; mt++) {
            int r0 = rowBase + wm * 32 + mt * 16 + g;
            int r1 = r0 + 8;
            float w0 = g_swt[r0], w1 = g_swt[r1];
            int t0 = g_rows[r0], t1 = g_rows[r1];
            float* p0 = C + (size_t)t0 * ldc;
            float* p1 = C + (size_t)t1 * ldc;
            #pragma unroll
            for (int nt = 0; nt < 8; nt++) {
                int cc = bn * 128 + wn * 64 + nt * 8 + 2 * t4;
                if (w0 != 0.f) {
                    atomicAdd(p0 + cc,     w0 * c[mt][nt][0]);
                    atomicAdd(p0 + cc + 1, w0 * c[mt][nt][1]);
                }
                if (w1 != 0.f) {
                    atomicAdd(p1 + cc,     w1 * c[mt][nt][2]);
                    atomicAdd(p1 + cc + 1, w1 * c[mt][nt][3]);
                }
            }
        }
    }
}

// ---------------- host ----------------
extern "C" void kernel_launch(void* const* d_in, const int* in_sizes, int n_in,
                              void* d_out, int out_size) {
    const float* x   = (const float*)d_in[0];
    const float* rw  = (const float*)d_in[1];
    const float* sw1 = (const float*)d_in[2];
    const float* sw2 = (const float*)d_in[3];
    const float* sw3 = (const float*)d_in[4];
    const float* ew1 = (const float*)d_in[5];
    const float* ew2 = (const float*)d_in[6];
    const float* ew3 = (const float*)d_in[7];
    float* out = (float*)d_out;

    __half *xh, *w13, *w2t, *e13, *e2t, *hS, *hR;
    cudaGetSymbolAddress((void**)&xh,  g_xh);
    cudaGetSymbolAddress((void**)&w13, g_w13T);
    cudaGetSymbolAddress((void**)&w2t, g_w2T);
    cudaGetSymbolAddress((void**)&e13, g_e13T);
    cudaGetSymbolAddress((void**)&e2t, g_e2T);
    cudaGetSymbolAddress((void**)&hS,  g_hS);
    cudaGetSymbolAddress((void**)&hR,  g_hR);

    cudaFuncSetAttribute(k_hgemm<1, false, false>, cudaFuncAttributeMaxDynamicSharedMemorySize, DYN_BYTES);
    cudaFuncSetAttribute(k_hgemm<1, true,  true >, cudaFuncAttributeMaxDynamicSharedMemorySize, DYN_BYTES);
    cudaFuncSetAttribute(k_hgemm<0, false, false>, cudaFuncAttributeMaxDynamicSharedMemorySize, DYN_BYTES);
    cudaFuncSetAttribute(k_hgemm<2, false, true >, cudaFuncAttributeMaxDynamicSharedMemorySize, DYN_BYTES);

    dim3 tb(256);
    // Launches 1-3, then GEMM1-shared as my launch #4 (ncu lands there).
    k_trans<<<dim3(HP / 64, DIMC / 64, 1), tb>>>(sw1, w13, DIMC, HIDC, HP, DIMC, 0, 0, 0);
    k_trans<<<dim3(HP / 64, DIMC / 64, 1), tb>>>(sw3, w13, DIMC, HIDC, HP, DIMC, 0, 0, 64);
    k_tohalf<<<((NTOK * DIMC / 4) + 255) / 256, 256>>>(x, xh, (long)NTOK * DIMC / 4);

    // ---- launch 4: shared GEMM1 (fused SwiGLU) — ncu capture target ----
    k_hgemm<1, false, false><<<dim3(HP2 / 128, NTOK / 128, 1), 256, DYN_BYTES>>>(
        xh, w13, hS, DIMC, DIMC, DIMC, HP, 0L);

    k_init<<<(MAXROWS + 255) / 256, 256>>>();
    k_router<<<(NTOK * 32 + 255) / 256, 256>>>(x, rw);

    // remaining prepass
    k_trans<<<dim3(DIMC / 64, HP / 64, 1), tb>>>(sw2, w2t, HIDC, DIMC, DIMC, HP, 0, 0, -1);
    k_trans<<<dim3(HP / 64, DIMC / 64, NEXP), tb>>>(ew1, e13, DIMC, HIDC, HP, DIMC,
                                                    (long)DIMC * HIDC, (long)HP2 * DIMC, 0);
    k_trans<<<dim3(HP / 64, DIMC / 64, NEXP), tb>>>(ew3, e13, DIMC, HIDC, HP, DIMC,
                                                    (long)DIMC * HIDC, (long)HP2 * DIMC, 64);
    k_trans<<<dim3(DIMC / 64, HP / 64, NEXP), tb>>>(ew2, e2t, HIDC, DIMC, DIMC, HP,
                                                    (long)HIDC * DIMC, (long)DIMC * HP, -1);
    k_scan<<<1, 32>>>();
    k_assign<<<(NTOK + 255) / 256, 256>>>();

    // ---- shared GEMM2 ----
    k_hgemm<0, false, false><<<dim3(DIMC / 128, NTOK / 128, 1), 256, DYN_BYTES>>>(
        hS, w2t, out, HP, HP, HP, DIMC, 0L);

    // ---- routed GEMM1 + GEMM2 (flat tile grids, in-kernel expert search) ----
    k_hgemm<1, true, true><<<dim3(HP2 / 128, MAXTILES, 1), 256, DYN_BYTES>>>(
        xh, e13, hR, DIMC, DIMC, DIMC, HP, (long)HP2 * DIMC);
    k_hgemm<2, false, true><<<dim3(DIMC / 128, MAXTILES, 1), 256, DYN_BYTES>>>(
        hR, e2t, out, HP, HP, HP, DIMC, (long)DIMC * HP);
}